// round 5
// baseline (speedup 1.0000x reference)
#include <cuda_runtime.h>

#define T_STEPS 4096
#define RES     2048
#define NF      8
#define NO      8
#define GRID_B  128
#define BLOCK_B 288    // 8 matvec warps + 1 finalize warp
#define NC      16     // output columns per CTA

// Scratch (allocation-free rule: device globals)
__device__ float g_drive[T_STEPS * RES];              // 32 MB
__device__ float g_X[T_STEPS * RES];                  // 32 MB
__device__ unsigned int g_flagrep[GRID_B * GRID_B];   // [consumer][producer], 64 KB

__device__ __forceinline__ unsigned long long ffma2(unsigned long long a,
                                                    unsigned long long b,
                                                    unsigned long long c) {
    unsigned long long d;
    asm("fma.rn.f32x2 %0, %1, %2, %3;" : "=l"(d) : "l"(a), "l"(b), "l"(c));
    return d;
}
__device__ __forceinline__ unsigned long long pack2(float x, float y) {
    unsigned long long d;
    asm("mov.b64 %0, {%1, %2};" : "=l"(d) : "f"(x), "f"(y));
    return d;
}
__device__ __forceinline__ unsigned ld_acquire(const unsigned int* p) {
    unsigned v;
    asm volatile("ld.acquire.gpu.global.u32 %0, [%1];" : "=r"(v) : "l"(p) : "memory");
    return v;
}
__device__ __forceinline__ void st_release(unsigned int* p, unsigned v) {
    asm volatile("st.release.gpu.global.u32 [%0], %1;" :: "l"(p), "r"(v) : "memory");
}

// ---------------------------------------------------------------------------
// Kernel A: drive[t][r] = win_bias[r] + inp[t] @ win_u[:, r]   (+ flag reset)
// ---------------------------------------------------------------------------
__global__ void drive_kernel(const float* __restrict__ inp,
                             const float* __restrict__ Win) {
    int t = blockIdx.y;
    int r = blockIdx.x * blockDim.x + threadIdx.x;
    if (blockIdx.y == 0 && blockIdx.x < 64)
        g_flagrep[blockIdx.x * 256 + threadIdx.x] = 0u;   // 64*256 = 16384 flags
    float acc = Win[r];                       // bias row (Win[0])
#pragma unroll
    for (int f = 0; f < NF; f++)
        acc += inp[t * NF + f] * Win[(1 + f) * RES + r];
    g_drive[t * RES + r] = acc;
}

// ---------------------------------------------------------------------------
// Kernel B: persistent scan, dataflow sync with PRIVATE per-consumer flags.
//   128 CTAs; warps 0-7 matvec (16 cols of W in regs, warp-private x slice),
//   warp 8 finalizes (tanh, x update, g_X store, flag fanout).
//   Warp w polls only its 16 producers' flags in ITS OWN 64B flag region ->
//   no shared hot L2 lines. One __syncthreads per step.
// ---------------------------------------------------------------------------
__global__ void __launch_bounds__(BLOCK_B, 1)
scan_kernel(const float* __restrict__ W) {
    __shared__ float sx[RES];                  // x_t; warp-private 256-slices
    __shared__ float sred[2][8][NC];           // partials, parity double-buffer

    const int tid  = threadIdx.x;
    const int w    = tid >> 5;
    const int lane = tid & 31;
    const int cb   = blockIdx.x;
    const int cbj  = cb * NC;                  // column base of this CTA

    const float dmp = 0.3f;
    const float omd = 1.0f - 0.3f;

    if (w < 8) {
        // ================= matvec warp =================
        const int col  = lane & 15;
        const int half = lane >> 4;
        const int jg   = cbj + col;
        const int i0   = w * 256 + half * 128;

        // one-time: W slice (128 rows x 1 col) into registers
        unsigned long long wrA[32], wrB[32];
#pragma unroll
        for (int k = 0; k < 32; k++) {
            int i = i0 + 4 * k;
            wrA[k] = pack2(__ldg(&W[(size_t)i * RES + jg]),
                           __ldg(&W[(size_t)(i + 1) * RES + jg]));
            wrB[k] = pack2(__ldg(&W[(size_t)(i + 2) * RES + jg]),
                           __ldg(&W[(size_t)(i + 3) * RES + jg]));
        }

        // x_0 = 0 (own slice)
        float4* sx4 = reinterpret_cast<float4*>(sx);
        sx4[w * 64 + lane]      = make_float4(0.f, 0.f, 0.f, 0.f);
        sx4[w * 64 + 32 + lane] = make_float4(0.f, 0.f, 0.f, 0.f);
        __syncwarp();

        const ulonglong2* sxu2 =
            reinterpret_cast<const ulonglong2*>(sx) + (w * 64 + half * 32);
        // private flag slot: consumer cb, producers w*16 .. w*16+15
        const unsigned int* fp = &g_flagrep[cb * GRID_B + w * 16 + (lane & 15)];

        for (int t = 0; t < T_STEPS; t++) {
            // ---- matvec partial: 32 broadcast LDS.128 + 64 fma.f32x2
            unsigned long long a0 = 0ull, a1 = 0ull, a2 = 0ull, a3 = 0ull;
#pragma unroll
            for (int k = 0; k < 32; k += 2) {
                ulonglong2 x0 = sxu2[k];
                ulonglong2 x1 = sxu2[k + 1];
                a0 = ffma2(wrA[k],     x0.x, a0);
                a1 = ffma2(wrB[k],     x0.y, a1);
                a2 = ffma2(wrA[k + 1], x1.x, a2);
                a3 = ffma2(wrB[k + 1], x1.y, a3);
            }
            float2 f0 = *reinterpret_cast<float2*>(&a0);
            float2 f1 = *reinterpret_cast<float2*>(&a1);
            float2 f2 = *reinterpret_cast<float2*>(&a2);
            float2 f3 = *reinterpret_cast<float2*>(&a3);
            float s = ((f0.x + f0.y) + (f1.x + f1.y)) +
                      ((f2.x + f2.y) + (f3.x + f3.y));
            s += __shfl_down_sync(0xffffffffu, s, 16);
            if (half == 0) sred[t & 1][w][col] = s;

            __syncthreads();                       // the ONE barrier per step
            if (t == T_STEPS - 1) break;

            // ---- poll own 16 producers (acquire loads on PRIVATE line)
            {
                const unsigned target = (unsigned)(t + 1);
                for (;;) {
                    unsigned v = (lane < 16) ? ld_acquire(fp) : target;
                    if (__all_sync(0xffffffffu, v >= target)) break;
                }
            }

            // ---- reload own warp-private 256-float slice of x_{t+1}
            const float4* src =
                reinterpret_cast<const float4*>(&g_X[(size_t)t * RES]) + w * 64;
            float4 v0 = __ldcg(&src[lane]);
            float4 v1 = __ldcg(&src[lane + 32]);
            sx4[w * 64 + lane]      = v0;
            sx4[w * 64 + 32 + lane] = v1;
            __syncwarp();
        }
    } else {
        // ================= finalize warp (warp 8) =================
        float xold = 0.0f;
        float drv  = (lane < NC) ? g_drive[cbj + lane] : 0.0f;   // t = 0

        for (int t = 0; t < T_STEPS; t++) {
            __syncthreads();                       // the ONE barrier per step

            if (lane < NC) {
                float tot = 0.0f;
#pragma unroll
                for (int ww = 0; ww < 8; ww++)
                    tot += sred[t & 1][ww][lane];
                float xn = omd * xold + dmp * tanhf(drv + tot);
                xold = xn;
                g_X[(size_t)t * RES + cbj + lane] = xn;
            }
            if (t == T_STEPS - 1) break;

            // prefetch next drive (hides behind fanout/next barrier)
            if (lane < NC)
                drv = __ldcg(&g_drive[(size_t)(t + 1) * RES + cbj + lane]);

            __syncwarp();   // order x stores (lanes 0-15) before fanout
            // ---- flag fanout: tag t+1 to all 128 consumers' private slots.
            //      release after syncwarp covers the warp's x stores (same
            //      bar+release composition R1 validated).
            {
                const unsigned tag = (unsigned)(t + 1);
                unsigned int* base = &g_flagrep[cb];   // + c*128
#pragma unroll
                for (int j = 0; j < 4; j++)
                    st_release(base + (lane + 32 * j) * GRID_B, tag);
            }
        }
    }
}

// ---------------------------------------------------------------------------
// Kernel C: Y[t] = wout_bias + inp[t] @ wout_u + x_{t+1} @ wout_x
// ---------------------------------------------------------------------------
__global__ void readout_kernel(const float* __restrict__ inp,
                               const float* __restrict__ Wout,
                               float* __restrict__ out) {
    const int w    = threadIdx.x >> 5;
    const int lane = threadIdx.x & 31;
    const int t    = blockIdx.x * 8 + w;

    float acc[NO];
#pragma unroll
    for (int o = 0; o < NO; o++) acc[o] = 0.0f;

    const float* xrow = &g_X[(size_t)t * RES];
    for (int it = 0; it < RES / 32; it++) {
        int r = it * 32 + lane;
        float xv = xrow[r];
        const float4* wrow =
            reinterpret_cast<const float4*>(&Wout[(size_t)(1 + NF + r) * NO]);
        float4 wa = wrow[0], wb = wrow[1];
        acc[0] += xv * wa.x; acc[1] += xv * wa.y;
        acc[2] += xv * wa.z; acc[3] += xv * wa.w;
        acc[4] += xv * wb.x; acc[5] += xv * wb.y;
        acc[6] += xv * wb.z; acc[7] += xv * wb.w;
    }
#pragma unroll
    for (int o = 0; o < NO; o++) {
#pragma unroll
        for (int sft = 16; sft > 0; sft >>= 1)
            acc[o] += __shfl_down_sync(0xffffffffu, acc[o], sft);
    }
    if (lane == 0) {
#pragma unroll
        for (int o = 0; o < NO; o++) {
            float y = Wout[o];
#pragma unroll
            for (int f = 0; f < NF; f++)
                y += inp[t * NF + f] * Wout[(1 + f) * NO + o];
            out[t * NO + o] = y + acc[o];
        }
    }
}

// ---------------------------------------------------------------------------
extern "C" void kernel_launch(void* const* d_in, const int* in_sizes, int n_in,
                              void* d_out, int out_size) {
    const float* inp  = (const float*)d_in[0];   // (4096, 8)
    const float* Win  = (const float*)d_in[1];   // (9, 2048)
    const float* W    = (const float*)d_in[2];   // (2048, 2048)
    const float* Wout = (const float*)d_in[3];   // (2057, 8)
    float* out = (float*)d_out;                  // (4096, 8) fp32

    dim3 ga(RES / 256, T_STEPS);
    drive_kernel<<<ga, 256>>>(inp, Win);
    scan_kernel<<<GRID_B, BLOCK_B>>>(W);
    readout_kernel<<<T_STEPS / 8, 256>>>(inp, Wout, out);
}

// round 6
// speedup vs baseline: 2.1137x; 2.1137x over previous
#include <cuda_runtime.h>

#define T_STEPS 4096
#define RES     2048
#define NF      8
#define NO      8
#define GRID_B  128
#define BLOCK_B 256
#define NC      16     // output columns per CTA

// Scratch (allocation-free rule: device globals)
__device__ float g_drive[T_STEPS * RES];   // 32 MB
__device__ float g_X[T_STEPS * RES];       // 32 MB
__device__ unsigned int g_counter;         // central arrival counter (R1-proven)

__device__ __forceinline__ unsigned long long ffma2(unsigned long long a,
                                                    unsigned long long b,
                                                    unsigned long long c) {
    unsigned long long d;
    asm("fma.rn.f32x2 %0, %1, %2, %3;" : "=l"(d) : "l"(a), "l"(b), "l"(c));
    return d;
}
__device__ __forceinline__ unsigned long long pack2(float x, float y) {
    unsigned long long d;
    asm("mov.b64 %0, {%1, %2};" : "=l"(d) : "f"(x), "f"(y));
    return d;
}

// ---------------------------------------------------------------------------
// Kernel A: drive[t][r] = win_bias[r] + inp[t] @ win_u[:, r]  (+ counter reset)
// ---------------------------------------------------------------------------
__global__ void drive_kernel(const float* __restrict__ inp,
                             const float* __restrict__ Win) {
    int t = blockIdx.y;
    int r = blockIdx.x * blockDim.x + threadIdx.x;
    if (blockIdx.x == 0 && blockIdx.y == 0 && threadIdx.x == 0) g_counter = 0u;
    float acc = Win[r];                       // bias row (Win[0])
#pragma unroll
    for (int f = 0; f < NF; f++)
        acc += inp[t * NF + f] * Win[(1 + f) * RES + r];
    g_drive[t * RES + r] = acc;
}

// ---------------------------------------------------------------------------
// Kernel B: persistent scan. R1's proven sync (ONE poller/CTA, central
// counter, everyone else asleep in BAR.SYNC) + optimized compute:
//   - 4 independent fma.f32x2 chains, LDS.128 x-broadcast
//   - warp-private sx slices -> reload needs only __syncwarp
//   - 2 block barriers per step (was 4), xold in registers, drive prefetch
// ---------------------------------------------------------------------------
__global__ void __launch_bounds__(BLOCK_B, 1)
scan_kernel(const float* __restrict__ W) {
    __shared__ float sx[RES];              // x_t; warp-private 256-slices
    __shared__ float sred[8][NC];          // per-warp partials

    const int tid  = threadIdx.x;
    const int w    = tid >> 5;
    const int lane = tid & 31;
    const int col  = lane & 15;
    const int half = lane >> 4;
    const int cb   = blockIdx.x;
    const int cbj  = cb * NC;              // column base of this CTA
    const int jg   = cbj + col;            // global output column
    const int i0   = w * 256 + half * 128; // this lane's 128-row chunk

    const float dmp = 0.3f;
    const float omd = 1.0f - 0.3f;

    // --- one-time: W slice (128 rows x 1 col) into registers
    unsigned long long wrA[32], wrB[32];
#pragma unroll
    for (int k = 0; k < 32; k++) {
        int i = i0 + 4 * k;
        wrA[k] = pack2(__ldg(&W[(size_t)i * RES + jg]),
                       __ldg(&W[(size_t)(i + 1) * RES + jg]));
        wrB[k] = pack2(__ldg(&W[(size_t)(i + 2) * RES + jg]),
                       __ldg(&W[(size_t)(i + 3) * RES + jg]));
    }

    // x_0 = 0 (own warp-private slice)
    float4* sx4 = reinterpret_cast<float4*>(sx);
    sx4[w * 64 + lane]      = make_float4(0.f, 0.f, 0.f, 0.f);
    sx4[w * 64 + 32 + lane] = make_float4(0.f, 0.f, 0.f, 0.f);
    __syncthreads();

    const ulonglong2* sxu2 =
        reinterpret_cast<const ulonglong2*>(sx) + (w * 64 + half * 32);

    float xold = 0.0f;   // warp 0 lanes 0-15: running x for own column

    for (int t = 0; t < T_STEPS; t++) {
        // finalize lanes: issue drive load early (resolves during matvec)
        float drv = 0.0f;
        if (w == 0 && lane < NC)
            drv = __ldcg(&g_drive[(size_t)t * RES + cbj + lane]);

        // ---- matvec partial: 32 broadcast LDS.128 + 64 fma.f32x2, 4 chains
        unsigned long long a0 = 0ull, a1 = 0ull, a2 = 0ull, a3 = 0ull;
#pragma unroll
        for (int k = 0; k < 32; k += 2) {
            ulonglong2 x0 = sxu2[k];
            ulonglong2 x1 = sxu2[k + 1];
            a0 = ffma2(wrA[k],     x0.x, a0);
            a1 = ffma2(wrB[k],     x0.y, a1);
            a2 = ffma2(wrA[k + 1], x1.x, a2);
            a3 = ffma2(wrB[k + 1], x1.y, a3);
        }
        float2 f0 = *reinterpret_cast<float2*>(&a0);
        float2 f1 = *reinterpret_cast<float2*>(&a1);
        float2 f2 = *reinterpret_cast<float2*>(&a2);
        float2 f3 = *reinterpret_cast<float2*>(&a3);
        float s = ((f0.x + f0.y) + (f1.x + f1.y)) +
                  ((f2.x + f2.y) + (f3.x + f3.y));
        s += __shfl_down_sync(0xffffffffu, s, 16);     // fold halves
        if (half == 0) sred[w][col] = s;

        __syncthreads();                                // bar 1

        if (w == 0) {
            // ---- finalize 16 columns -> x_{t+1} -> g_X, release, poll
            if (lane < NC) {
                float tot = 0.0f;
#pragma unroll
                for (int ww = 0; ww < 8; ww++) tot += sred[ww][lane];
                float xn = omd * xold + dmp * tanhf(drv + tot);
                xold = xn;
                g_X[(size_t)t * RES + cbj + lane] = xn;
            }
            if (t < T_STEPS - 1) {
                __syncwarp();                 // order lanes' STGs before release
                if (lane == 0) {
                    asm volatile("red.release.gpu.add.u32 [%0], %1;"
                                 :: "l"(&g_counter), "r"(1u) : "memory");
                    unsigned target = (unsigned)GRID_B * (unsigned)(t + 1);
                    unsigned v;
                    do {
                        asm volatile("ld.acquire.gpu.u32 %0, [%1];"
                                     : "=r"(v) : "l"(&g_counter) : "memory");
                    } while (v < target);
                }
            }
        }
        if (t == T_STEPS - 1) break;
        __syncthreads();                                // bar 2

        // ---- reload own warp-private 256-float slice of x_{t+1}
        const float4* src =
            reinterpret_cast<const float4*>(&g_X[(size_t)t * RES]) + w * 64;
        float4 v0 = __ldcg(&src[lane]);
        float4 v1 = __ldcg(&src[lane + 32]);
        sx4[w * 64 + lane]      = v0;
        sx4[w * 64 + 32 + lane] = v1;
        __syncwarp();
    }
}

// ---------------------------------------------------------------------------
// Kernel C: Y[t] = wout_bias + inp[t] @ wout_u + x_{t+1} @ wout_x
// ---------------------------------------------------------------------------
__global__ void readout_kernel(const float* __restrict__ inp,
                               const float* __restrict__ Wout,
                               float* __restrict__ out) {
    const int w    = threadIdx.x >> 5;
    const int lane = threadIdx.x & 31;
    const int t    = blockIdx.x * 8 + w;

    float acc[NO];
#pragma unroll
    for (int o = 0; o < NO; o++) acc[o] = 0.0f;

    const float* xrow = &g_X[(size_t)t * RES];
    for (int it = 0; it < RES / 32; it++) {
        int r = it * 32 + lane;
        float xv = xrow[r];
        const float4* wrow =
            reinterpret_cast<const float4*>(&Wout[(size_t)(1 + NF + r) * NO]);
        float4 wa = wrow[0], wb = wrow[1];
        acc[0] += xv * wa.x; acc[1] += xv * wa.y;
        acc[2] += xv * wa.z; acc[3] += xv * wa.w;
        acc[4] += xv * wb.x; acc[5] += xv * wb.y;
        acc[6] += xv * wb.z; acc[7] += xv * wb.w;
    }
#pragma unroll
    for (int o = 0; o < NO; o++) {
#pragma unroll
        for (int sft = 16; sft > 0; sft >>= 1)
            acc[o] += __shfl_down_sync(0xffffffffu, acc[o], sft);
    }
    if (lane == 0) {
#pragma unroll
        for (int o = 0; o < NO; o++) {
            float y = Wout[o];
#pragma unroll
            for (int f = 0; f < NF; f++)
                y += inp[t * NF + f] * Wout[(1 + f) * NO + o];
            out[t * NO + o] = y + acc[o];
        }
    }
}

// ---------------------------------------------------------------------------
extern "C" void kernel_launch(void* const* d_in, const int* in_sizes, int n_in,
                              void* d_out, int out_size) {
    const float* inp  = (const float*)d_in[0];   // (4096, 8)
    const float* Win  = (const float*)d_in[1];   // (9, 2048)
    const float* W    = (const float*)d_in[2];   // (2048, 2048)
    const float* Wout = (const float*)d_in[3];   // (2057, 8)
    float* out = (float*)d_out;                  // (4096, 8) fp32

    dim3 ga(RES / 256, T_STEPS);
    drive_kernel<<<ga, 256>>>(inp, Win);
    scan_kernel<<<GRID_B, BLOCK_B>>>(W);
    readout_kernel<<<T_STEPS / 8, 256>>>(inp, Wout, out);
}

// round 7
// speedup vs baseline: 3.6954x; 1.7483x over previous
#include <cuda_runtime.h>

#define T_STEPS 4096
#define RES     2048
#define NF      8
#define NO      8
#define GRID_B  128
#define BLOCK_B 256
#define NC      16            // output columns per CTA
#define SENT    0xFFC00000u   // negative NaN — real x is finite, never this

// Scratch (allocation-free rule: device globals)
__device__ float g_drive[T_STEPS * RES];   // 32 MB
__device__ float g_X[T_STEPS * RES];       // 32 MB, sentinel-poisoned each run

__device__ __forceinline__ unsigned long long ffma2(unsigned long long a,
                                                    unsigned long long b,
                                                    unsigned long long c) {
    unsigned long long d;
    asm("fma.rn.f32x2 %0, %1, %2, %3;" : "=l"(d) : "l"(a), "l"(b), "l"(c));
    return d;
}
__device__ __forceinline__ unsigned long long pack2(float x, float y) {
    unsigned long long d;
    asm("mov.b64 %0, {%1, %2};" : "=l"(d) : "f"(x), "f"(y));
    return d;
}
__device__ __forceinline__ uint4 ldv_u4(const uint4* p) {
    uint4 v;
    asm volatile("ld.volatile.global.v4.u32 {%0,%1,%2,%3}, [%4];"
                 : "=r"(v.x), "=r"(v.y), "=r"(v.z), "=r"(v.w) : "l"(p));
    return v;
}

// ---------------------------------------------------------------------------
// Kernel A: drive[t][r] = win_bias[r] + inp[t] @ win_u[:, r]
//           + poison g_X[t][r] with the sentinel (re-done every run)
// ---------------------------------------------------------------------------
__global__ void drive_kernel(const float* __restrict__ inp,
                             const float* __restrict__ Win) {
    int t = blockIdx.y;
    int r = blockIdx.x * blockDim.x + threadIdx.x;
    reinterpret_cast<unsigned int*>(g_X)[(size_t)t * RES + r] = SENT;
    float acc = Win[r];                       // bias row (Win[0])
#pragma unroll
    for (int f = 0; f < NF; f++)
        acc += inp[t * NF + f] * Win[(1 + f) * RES + r];
    g_drive[t * RES + r] = acc;
}

// ---------------------------------------------------------------------------
// Kernel B: persistent scan, dataflow sync by POLLING THE DATA.
//   128 CTAs x 256 thr; each CTA owns 16 columns of W in registers.
//   No flags, no counters, no fences: g_X is a monotone t-buffer, poisoned
//   with SENT; warp w volatile-polls its own 256-float slice of g_X[t] and
//   proceeds the moment every word is real. One __syncthreads per step.
// ---------------------------------------------------------------------------
__global__ void __launch_bounds__(BLOCK_B, 1)
scan_kernel(const float* __restrict__ W) {
    __shared__ float sx[RES];              // x_t; warp-private 256-slices
    __shared__ float sred[2][8][NC];       // partials, parity double-buffered

    const int tid  = threadIdx.x;
    const int w    = tid >> 5;
    const int lane = tid & 31;
    const int col  = lane & 15;
    const int half = lane >> 4;
    const int cb   = blockIdx.x;
    const int cbj  = cb * NC;              // column base of this CTA
    const int jg   = cbj + col;            // global output column
    const int i0   = w * 256 + half * 128; // this lane's 128-row chunk

    const float dmp = 0.3f;
    const float omd = 1.0f - 0.3f;

    // --- one-time: W slice (128 rows x 1 col) into registers
    unsigned long long wrA[32], wrB[32];
#pragma unroll
    for (int k = 0; k < 32; k++) {
        int i = i0 + 4 * k;
        wrA[k] = pack2(__ldg(&W[(size_t)i * RES + jg]),
                       __ldg(&W[(size_t)(i + 1) * RES + jg]));
        wrB[k] = pack2(__ldg(&W[(size_t)(i + 2) * RES + jg]),
                       __ldg(&W[(size_t)(i + 3) * RES + jg]));
    }

    // x_0 = 0 (own warp-private slice)
    float4* sx4 = reinterpret_cast<float4*>(sx);
    sx4[w * 64 + lane]      = make_float4(0.f, 0.f, 0.f, 0.f);
    sx4[w * 64 + 32 + lane] = make_float4(0.f, 0.f, 0.f, 0.f);
    __syncthreads();

    const ulonglong2* sxu2 =
        reinterpret_cast<const ulonglong2*>(sx) + (w * 64 + half * 32);

    float xold = 0.0f;   // warp 0 lanes 0-15: running x for own column
    float drv  = 0.0f;   // warp 0 lanes 0-15: prefetched drive
    if (w == 0 && lane < NC) drv = __ldcg(&g_drive[cbj + lane]);

    for (int t = 0; t < T_STEPS; t++) {
        // ---- matvec partial: 32 broadcast LDS.128 + 64 fma.f32x2, 4 chains
        unsigned long long a0 = 0ull, a1 = 0ull, a2 = 0ull, a3 = 0ull;
#pragma unroll
        for (int k = 0; k < 32; k += 2) {
            ulonglong2 x0 = sxu2[k];
            ulonglong2 x1 = sxu2[k + 1];
            a0 = ffma2(wrA[k],     x0.x, a0);
            a1 = ffma2(wrB[k],     x0.y, a1);
            a2 = ffma2(wrA[k + 1], x1.x, a2);
            a3 = ffma2(wrB[k + 1], x1.y, a3);
        }
        float2 f0 = *reinterpret_cast<float2*>(&a0);
        float2 f1 = *reinterpret_cast<float2*>(&a1);
        float2 f2 = *reinterpret_cast<float2*>(&a2);
        float2 f3 = *reinterpret_cast<float2*>(&a3);
        float s = ((f0.x + f0.y) + (f1.x + f1.y)) +
                  ((f2.x + f2.y) + (f3.x + f3.y));
        s += __shfl_down_sync(0xffffffffu, s, 16);     // fold halves
        if (half == 0) sred[t & 1][w][col] = s;

        __syncthreads();                                // ONE barrier per step

        // ---- finalize (warp 0, lanes 0-15): tanh update, publish x_{t+1}
        if (w == 0 && lane < NC) {
            float tot = 0.0f;
#pragma unroll
            for (int ww = 0; ww < 8; ww++) tot += sred[t & 1][ww][lane];
            float xn = omd * xold + dmp * tanhf(drv + tot);
            xold = xn;
            __stcg(&g_X[(size_t)t * RES + cbj + lane], xn);   // the "signal"
            if (t < T_STEPS - 1)
                drv = __ldcg(&g_drive[(size_t)(t + 1) * RES + cbj + lane]);
        }
        if (t == T_STEPS - 1) break;

        // ---- dataflow gather: poll own 256-float slice of g_X[t] until
        //      every word is non-sentinel, then stage into smem.
        {
            const uint4* src =
                reinterpret_cast<const uint4*>(&g_X[(size_t)t * RES]) + w * 64;
            uint4 v0, v1;
            for (;;) {
                v0 = ldv_u4(src + lane);
                v1 = ldv_u4(src + lane + 32);
                bool ok = (v0.x != SENT) & (v0.y != SENT) &
                          (v0.z != SENT) & (v0.w != SENT) &
                          (v1.x != SENT) & (v1.y != SENT) &
                          (v1.z != SENT) & (v1.w != SENT);
                if (__all_sync(0xffffffffu, ok)) break;
            }
            sx4[w * 64 + lane]      = *reinterpret_cast<float4*>(&v0);
            sx4[w * 64 + 32 + lane] = *reinterpret_cast<float4*>(&v1);
            __syncwarp();
        }
    }
}

// ---------------------------------------------------------------------------
// Kernel C: Y[t] = wout_bias + inp[t] @ wout_u + x_{t+1} @ wout_x
// ---------------------------------------------------------------------------
__global__ void readout_kernel(const float* __restrict__ inp,
                               const float* __restrict__ Wout,
                               float* __restrict__ out) {
    const int w    = threadIdx.x >> 5;
    const int lane = threadIdx.x & 31;
    const int t    = blockIdx.x * 8 + w;

    float acc[NO];
#pragma unroll
    for (int o = 0; o < NO; o++) acc[o] = 0.0f;

    const float* xrow = &g_X[(size_t)t * RES];
    for (int it = 0; it < RES / 32; it++) {
        int r = it * 32 + lane;
        float xv = xrow[r];
        const float4* wrow =
            reinterpret_cast<const float4*>(&Wout[(size_t)(1 + NF + r) * NO]);
        float4 wa = wrow[0], wb = wrow[1];
        acc[0] += xv * wa.x; acc[1] += xv * wa.y;
        acc[2] += xv * wa.z; acc[3] += xv * wa.w;
        acc[4] += xv * wb.x; acc[5] += xv * wb.y;
        acc[6] += xv * wb.z; acc[7] += xv * wb.w;
    }
#pragma unroll
    for (int o = 0; o < NO; o++) {
#pragma unroll
        for (int sft = 16; sft > 0; sft >>= 1)
            acc[o] += __shfl_down_sync(0xffffffffu, acc[o], sft);
    }
    if (lane == 0) {
#pragma unroll
        for (int o = 0; o < NO; o++) {
            float y = Wout[o];
#pragma unroll
            for (int f = 0; f < NF; f++)
                y += inp[t * NF + f] * Wout[(1 + f) * NO + o];
            out[t * NO + o] = y + acc[o];
        }
    }
}

// ---------------------------------------------------------------------------
extern "C" void kernel_launch(void* const* d_in, const int* in_sizes, int n_in,
                              void* d_out, int out_size) {
    const float* inp  = (const float*)d_in[0];   // (4096, 8)
    const float* Win  = (const float*)d_in[1];   // (9, 2048)
    const float* W    = (const float*)d_in[2];   // (2048, 2048)
    const float* Wout = (const float*)d_in[3];   // (2057, 8)
    float* out = (float*)d_out;                  // (4096, 8) fp32

    dim3 ga(RES / 256, T_STEPS);
    drive_kernel<<<ga, 256>>>(inp, Win);         // also poisons g_X
    scan_kernel<<<GRID_B, BLOCK_B>>>(W);
    readout_kernel<<<T_STEPS / 8, 256>>>(inp, Wout, out);
}